// round 13
// baseline (speedup 1.0000x reference)
#include <cuda_runtime.h>
#include <cuda_fp16.h>
#include <cstdint>

// ---------------- problem dims ----------------
#define BB 64
#define TT 512
#define II 128
#define NN 2048
#define NTILES 16
#define KSP 9                 // 8 recurrent k-slices of 256 + 1 input slice
#define KSLICE 256
#define NSL 9                 // partial slices (wk pair pre-combined in CTA)
#define GRID (NTILES * KSP)   // 144 CTAs, co-resident (1 per SM)
#define NTHREADS 256

// ---------------- smem layout (bytes) ----------------
#define A_STRIDE 528                       // 256 fp16 + 16B pad
#define B_STRIDE 144                       // 64 fp16 + 16B pad
#define A_OFF 0
#define B_OFF (128 * A_STRIDE)             // 67584
#define SMEM_DYN (B_OFF + 256 * B_STRIDE)  // 104448
// exchange region aliases B after MMA: 128 thr * 68 floats = 34816 B <= 36864

// ---------------- device globals ----------------
__device__ float g_h[2][NN * BB];                // hidden state ping-pong, [n][b]
__device__ float g_partial[NSL][NN * BB];        // split-K partials
__device__ __half g_r16[NN * BB];                // relu(h) fp16, [n][b]
__device__ __half g_x16[TT * II * BB];           // x fp16, [t][i][b]
__device__ unsigned int g_arrive;

// ---------------- helpers ----------------
__device__ __forceinline__ uint32_t smem_u32(const void* p) {
    uint32_t a;
    asm("{ .reg .u64 t; cvta.to.shared.u64 t, %1; cvt.u32.u64 %0, t; }" : "=r"(a) : "l"(p));
    return a;
}
__device__ __forceinline__ void ldsm4(uint32_t* r, uint32_t addr) {
    asm volatile("ldmatrix.sync.aligned.m8n8.x4.shared.b16 {%0,%1,%2,%3}, [%4];"
                 : "=r"(r[0]), "=r"(r[1]), "=r"(r[2]), "=r"(r[3]) : "r"(addr));
}
__device__ __forceinline__ void ldsm4t(uint32_t* r, uint32_t addr) {
    asm volatile("ldmatrix.sync.aligned.m8n8.x4.trans.shared.b16 {%0,%1,%2,%3}, [%4];"
                 : "=r"(r[0]), "=r"(r[1]), "=r"(r[2]), "=r"(r[3]) : "r"(addr));
}
__device__ __forceinline__ void mma16816(float* d, const uint32_t* a, const uint32_t* b) {
    asm volatile(
        "mma.sync.aligned.m16n8k16.row.col.f32.f16.f16.f32 "
        "{%0,%1,%2,%3}, {%4,%5,%6,%7}, {%8,%9}, {%0,%1,%2,%3};"
        : "+f"(d[0]), "+f"(d[1]), "+f"(d[2]), "+f"(d[3])
        : "r"(a[0]), "r"(a[1]), "r"(a[2]), "r"(a[3]), "r"(b[0]), "r"(b[1]));
}
__device__ __forceinline__ void sig_add(unsigned int* p, unsigned int v) {
    asm volatile("red.release.gpu.global.add.u32 [%0], %1;" :: "l"(p), "r"(v) : "memory");
}
__device__ __forceinline__ unsigned int ld_acq(const unsigned int* p) {
    unsigned int v;
    asm volatile("ld.acquire.gpu.global.u32 %0, [%1];" : "=r"(v) : "l"(p) : "memory");
    return v;
}
__device__ __forceinline__ void poll_ge(const unsigned int* p, unsigned int tgt) {
    while (ld_acq(p) < tgt) { __nanosleep(32); }
}
__device__ __forceinline__ void cp16(uint32_t dst, const void* src) {
    asm volatile("cp.async.cg.shared.global [%0], [%1], 16;" :: "r"(dst), "l"(src) : "memory");
}
__device__ __forceinline__ void cp_commit() {
    asm volatile("cp.async.commit_group;" ::: "memory");
}
__device__ __forceinline__ void cp_waitg0() {
    asm volatile("cp.async.wait_group 0;" ::: "memory");
}
__device__ __forceinline__ void cp_waitg1() {
    asm volatile("cp.async.wait_group 1;" ::: "memory");
}
__device__ __forceinline__ void named_bar(int id) {
    asm volatile("bar.sync %0, 128;" :: "r"(id) : "memory");
}

// ---------------- persistent RNN kernel ----------------
__global__ void __launch_bounds__(NTHREADS, 1) rnn_persistent(
    const float* __restrict__ x,      // [B,T,I]
    const float* __restrict__ h0,     // [B,N]
    const float* __restrict__ Wrec,   // [N,N]
    const float* __restrict__ Winp,   // [N,I]
    const float* __restrict__ tonic,  // [N]
    const int*   __restrict__ mask,   // [N,N]
    const int*   __restrict__ sgn,    // [N,N]
    float* __restrict__ out)          // [B,T,N]
{
    extern __shared__ __align__(16) char sm[];
    const uint32_t smb = smem_u32(sm);
    __shared__ float sm_out[64][25];   // out staging [b][row], rows<=24

    const int cta = blockIdx.x;
    const int nt  = cta % NTILES;
    const int ks  = cta / NTILES;
    const int n0  = nt * 128;
    const int k0  = ks * KSLICE;
    const int tid = threadIdx.x;
    const int wid = tid >> 5;
    const int lane = tid & 31;
    const int wg_tid = tid & 127;
    const bool inp = (ks == KSP - 1);

    // warp grid: wm = wid&3 (32-row slabs), wk = wid>>2 (k halves)
    const int wm = wid & 3;
    const int wk = wid >> 2;
    const int KS = inp ? 4 : 8;            // ksteps per warp (half K)
    const int KH = KS >> 1;                // ksteps per chunk
    const int kkbase = wk * KS;

    // ======== prologue (once per launch) ========
    // A (W slice) -> smem, single fp16 plane
    for (int idx = tid; idx < 128 * 256; idx += NTHREADS) {
        int m = idx >> 8, c = idx & 255;
        int n = n0 + m;
        float v = 0.0f;
        if (!inp) {
            int k = k0 + c;
            float w = Wrec[(size_t)n * NN + k];
            int ms = mask[(size_t)n * NN + k] * sgn[(size_t)n * NN + k];
            v = fmaxf(w, 0.0f) * (float)ms;
        } else if (c < II) {
            v = Winp[(size_t)n * II + c];
        }
        *(__half*)(sm + A_OFF + m * A_STRIDE + c * 2) = __float2half(v);
    }
    // h0 -> g_h[0] and g_r16 ([n][b] layout)
    {
        int gid = cta * NTHREADS + tid;
        if (gid < (NN * BB) / 4) {
            int base = gid * 4;
            int n = base >> 6, b0 = base & 63;
            float hv[4];
#pragma unroll
            for (int u = 0; u < 4; ++u) hv[u] = h0[(size_t)(b0 + u) * NN + n];
            *(float4*)&g_h[0][base] = make_float4(hv[0], hv[1], hv[2], hv[3]);
            __half2 r01 = __floats2half2_rn(fmaxf(hv[0], 0.f), fmaxf(hv[1], 0.f));
            __half2 r23 = __floats2half2_rn(fmaxf(hv[2], 0.f), fmaxf(hv[3], 0.f));
            uint2 pk;
            pk.x = *(uint32_t*)&r01;
            pk.y = *(uint32_t*)&r23;
            *(uint2*)&g_r16[base] = pk;
        }
    }
    // x -> g_x16 ([t][i][b] layout)
    for (int gid = cta * NTHREADS + tid; gid < (TT * II * BB) / 4; gid += GRID * NTHREADS) {
        int base = gid * 4;
        int b0 = base & 63;
        int i  = (base >> 6) & (II - 1);
        int t  = base >> 13;
        float v0 = __ldg(&x[((size_t)(b0 + 0) * TT + t) * II + i]);
        float v1 = __ldg(&x[((size_t)(b0 + 1) * TT + t) * II + i]);
        float v2 = __ldg(&x[((size_t)(b0 + 2) * TT + t) * II + i]);
        float v3 = __ldg(&x[((size_t)(b0 + 3) * TT + t) * II + i]);
        __half2 x01 = __floats2half2_rn(v0, v1);
        __half2 x23 = __floats2half2_rn(v2, v3);
        uint2 pk;
        pk.x = *(uint32_t*)&x01;
        pk.y = *(uint32_t*)&x23;
        *(uint2*)&g_x16[base] = pk;
    }
    __syncthreads();

    // ---- preload A fragments into registers (persist all 512 steps) ----
    const uint32_t aBase = smb + A_OFF
        + (uint32_t)(wm * 32 + (lane & 15)) * A_STRIDE + (uint32_t)(lane >> 4) * 16;
    uint32_t af[8][2][4];                  // [kstep][mt][4]
#pragma unroll
    for (int j = 0; j < 8; ++j) {
        if (j < KS) {
            const uint32_t aA = aBase + (uint32_t)(kkbase + j) * 32;
            ldsm4(af[j][0], aA);
            ldsm4(af[j][1], aA + 16 * A_STRIDE);
        } else {
#pragma unroll
            for (int mt = 0; mt < 2; ++mt)
#pragma unroll
                for (int q = 0; q < 4; ++q) af[j][mt][q] = 0u;
        }
    }

    // prologue barrier
    unsigned int bar = GRID;
    __threadfence();
    __syncthreads();
    if (tid == 0) { sig_add(&g_arrive, 1u); poll_ge(&g_arrive, bar); }
    __syncthreads();

    // B fragment base (covers all 64 cols per warp)
    const uint32_t bBase = smb + B_OFF
        + (uint32_t)((lane & 7) + ((lane >> 3) & 1) * 8) * B_STRIDE
        + (uint32_t)(lane >> 4) * 16;

    // reduce ownership (input CTAs take more rows)
    const int Rrows = inp ? 24 : 13;
    const int nbase = inp ? (1664 + nt * 24) : (cta * 13);

    const float AC = 0.1f, OMA = 0.9f;
    float* ex = (float*)(sm + B_OFF);      // exchange, aliases B

    for (int t = 0; t < TT; ++t) {
        const float* __restrict__ cur = g_h[t & 1];
        float* __restrict__ nxt = g_h[(t + 1) & 1];

        // ---- phase 1: B-copy (single fp16 plane) in 2 committed chunks ----
        const char* src = inp ? (const char*)&g_x16[(size_t)t * II * BB]
                              : (const char*)&g_r16[(size_t)k0 * BB];
        const int half_rows = inp ? 64 : 128;   // rows per wk half
        const int crows = half_rows >> 1;       // rows per chunk
        const int row0 = wk * half_rows;
#pragma unroll
        for (int ch = 0; ch < 2; ++ch) {
            const int r0c = row0 + ch * crows;
            for (int s = wg_tid; s < crows * 8; s += 128) {
                int r = r0c + (s >> 3), c16 = (s & 7) * 16;
                cp16(smb + B_OFF + r * B_STRIDE + c16, src + r * 128 + c16);
            }
            cp_commit();
        }

        // ---- phase 2: 1-term fp16 MMA (A in regs, B from smem) ----
        float acc[2][8][4];
#pragma unroll
        for (int a = 0; a < 2; ++a)
#pragma unroll
            for (int b = 0; b < 8; ++b)
#pragma unroll
                for (int q = 0; q < 4; ++q) acc[a][b][q] = 0.0f;

        cp_waitg1();
        named_bar(1 + wk);

#pragma unroll
        for (int half = 0; half < 2; ++half) {
#pragma unroll
            for (int j = half * 2; j < half * 2 + 2; ++j) {   // KH<=4: loop split below
            }
            // process ksteps [half*KH, half*KH+KH)
#pragma unroll 2
            for (int j = 0; j < 4; ++j) {
                const int js = half * KH + j;
                if (j < KH) {
                    const int kk = kkbase + js;
                    uint32_t bf[8][2];
                    const uint32_t bA = bBase + (uint32_t)kk * 16 * B_STRIDE;
                    ldsm4t(&bf[0][0], bA);
                    ldsm4t(&bf[2][0], bA + 32);
                    ldsm4t(&bf[4][0], bA + 64);
                    ldsm4t(&bf[6][0], bA + 96);
#pragma unroll
                    for (int mt = 0; mt < 2; ++mt)
#pragma unroll
                        for (int nb = 0; nb < 8; ++nb)
                            mma16816(acc[mt][nb], af[js][mt], bf[nb]);
                }
            }
            if (half == 0) {
                cp_waitg0();
                named_bar(1 + wk);
            }
        }

        // ---- phase 3: wk-pair combine in smem, then store slice ks ----
        __syncthreads();                   // all B-frag reads complete
        if (wk == 1) {
#pragma unroll
            for (int mt = 0; mt < 2; ++mt)
#pragma unroll
                for (int nb = 0; nb < 8; ++nb)
                    *(float4*)&ex[wg_tid * 68 + (mt * 8 + nb) * 4] =
                        make_float4(acc[mt][nb][0], acc[mt][nb][1],
                                    acc[mt][nb][2], acc[mt][nb][3]);
        }
        __syncthreads();
        if (wk == 0) {
            float* dst = &g_partial[ks][0];
            const int gi = lane >> 2;
            const int ti = lane & 3;
#pragma unroll
            for (int mt = 0; mt < 2; ++mt) {
                int r0 = n0 + wm * 32 + mt * 16 + gi;
#pragma unroll
                for (int nb = 0; nb < 8; ++nb) {
                    float4 o = *(float4*)&ex[wg_tid * 68 + (mt * 8 + nb) * 4];
                    int cb = nb * 8 + 2 * ti;
                    __stcg((float2*)&dst[(size_t)r0 * BB + cb],
                           make_float2(acc[mt][nb][0] + o.x, acc[mt][nb][1] + o.y));
                    __stcg((float2*)&dst[(size_t)(r0 + 8) * BB + cb],
                           make_float2(acc[mt][nb][2] + o.z, acc[mt][nb][3] + o.w));
                }
            }
        }

        // ---- barrier 1: partials visible ----
        bar += GRID;
        __syncthreads();
        if (tid == 0) { sig_add(&g_arrive, 1u); poll_ge(&g_arrive, bar); }
        __syncthreads();

        // ---- phase 4: distributed reduce + update + relu + publish r ----
        for (int u = tid; u < Rrows * 16; u += NTHREADS) {
            int row = u >> 4;
            int b0 = (u & 15) * 4;
            int n = nbase + row;
            size_t off = (size_t)n * BB + b0;

            float4 s = make_float4(0.f, 0.f, 0.f, 0.f);
#pragma unroll
            for (int p = 0; p < NSL; ++p) {
                float4 q = __ldcg((const float4*)&g_partial[p][off]);
                s.x += q.x; s.y += q.y; s.z += q.z; s.w += q.w;
            }
            float tn = __ldg(&tonic[n]);
            float4 hv = __ldcg((const float4*)&cur[off]);
            float4 r4;
            r4.x = OMA * hv.x + AC * (s.x + tn);
            r4.y = OMA * hv.y + AC * (s.y + tn);
            r4.z = OMA * hv.z + AC * (s.z + tn);
            r4.w = OMA * hv.w + AC * (s.w + tn);
            __stcg((float4*)&nxt[off], r4);

            float rr[4] = {fmaxf(r4.x, 0.f), fmaxf(r4.y, 0.f),
                           fmaxf(r4.z, 0.f), fmaxf(r4.w, 0.f)};
            sm_out[b0 + 0][row] = rr[0];
            sm_out[b0 + 1][row] = rr[1];
            sm_out[b0 + 2][row] = rr[2];
            sm_out[b0 + 3][row] = rr[3];

            __half2 r01 = __floats2half2_rn(rr[0], rr[1]);
            __half2 r23 = __floats2half2_rn(rr[2], rr[3]);
            uint2 pk;
            pk.x = *(uint32_t*)&r01;
            pk.y = *(uint32_t*)&r23;
            *(uint2*)&g_r16[off] = pk;
        }

        // ---- barrier 2 with out-writes overlapped into the wait ----
        bar += GRID;
        __syncthreads();
        if (tid == 0) sig_add(&g_arrive, 1u);
        for (int idx = tid; idx < Rrows * 64; idx += NTHREADS) {
            int b = idx / Rrows;
            int rr2 = idx - b * Rrows;
            out[((size_t)b * TT + t) * NN + nbase + rr2] = sm_out[b][rr2];
        }
        if (tid == 0) poll_ge(&g_arrive, bar);
        __syncthreads();
    }
}

// ---------------- launch ----------------
extern "C" void kernel_launch(void* const* d_in, const int* in_sizes, int n_in,
                              void* d_out, int out_size) {
    const float* x     = (const float*)d_in[0];
    const float* h0    = (const float*)d_in[1];
    const float* Wrec  = (const float*)d_in[2];
    const float* Winp  = (const float*)d_in[3];
    const float* tonic = (const float*)d_in[4];
    const int*   mask  = (const int*)d_in[5];
    const int*   sgn   = (const int*)d_in[6];
    float* out = (float*)d_out;

    cudaFuncSetAttribute(rnn_persistent,
                         cudaFuncAttributeMaxDynamicSharedMemorySize, SMEM_DYN);

    void* pa = nullptr;
    cudaGetSymbolAddress(&pa, g_arrive);
    cudaMemsetAsync(pa, 0, sizeof(unsigned int));

    rnn_persistent<<<GRID, NTHREADS, SMEM_DYN>>>(x, h0, Wrec, Winp, tonic,
                                                 mask, sgn, out);
}

// round 14
// speedup vs baseline: 1.1859x; 1.1859x over previous
#include <cuda_runtime.h>
#include <cuda_fp16.h>
#include <cstdint>

// ---------------- problem dims ----------------
#define BB 64
#define TT 512
#define II 128
#define NN 2048
#define NTILES 16
#define KSP 9                 // 8 recurrent k-slices of 256 + 1 input slice
#define KSLICE 256
#define NSL 9                 // partial slices (wk pair pre-combined in CTA)
#define GRID (NTILES * KSP)   // 144 CTAs, co-resident (1 per SM)
#define NTHREADS 256

// ---------------- smem layout (bytes) ----------------
#define A_STRIDE 528                       // 256 fp16 + 16B pad
#define B_STRIDE 144                       // 64 fp16 + 16B pad
#define A_OFF 0
#define B_OFF (128 * A_STRIDE)             // 67584
#define SMEM_DYN (B_OFF + 256 * B_STRIDE)  // 104448
// exchange region aliases B after MMA: 128 thr * 68 floats = 34816 B <= 36864

// ---------------- device globals ----------------
__device__ float g_h[2][NN * BB];                // hidden state ping-pong, [n][b]
__device__ float g_partial[NSL][NN * BB];        // split-K partials
__device__ __half g_r16[NN * BB];                // relu(h) fp16, [n][b]
__device__ __half g_x16[TT * II * BB];           // x fp16, [t][i][b]
__device__ unsigned int g_arrive;

// ---------------- helpers ----------------
__device__ __forceinline__ uint32_t smem_u32(const void* p) {
    uint32_t a;
    asm("{ .reg .u64 t; cvta.to.shared.u64 t, %1; cvt.u32.u64 %0, t; }" : "=r"(a) : "l"(p));
    return a;
}
__device__ __forceinline__ void ldsm4(uint32_t* r, uint32_t addr) {
    asm volatile("ldmatrix.sync.aligned.m8n8.x4.shared.b16 {%0,%1,%2,%3}, [%4];"
                 : "=r"(r[0]), "=r"(r[1]), "=r"(r[2]), "=r"(r[3]) : "r"(addr));
}
__device__ __forceinline__ void ldsm4t(uint32_t* r, uint32_t addr) {
    asm volatile("ldmatrix.sync.aligned.m8n8.x4.trans.shared.b16 {%0,%1,%2,%3}, [%4];"
                 : "=r"(r[0]), "=r"(r[1]), "=r"(r[2]), "=r"(r[3]) : "r"(addr));
}
__device__ __forceinline__ void mma16816(float* d, const uint32_t* a, const uint32_t* b) {
    asm volatile(
        "mma.sync.aligned.m16n8k16.row.col.f32.f16.f16.f32 "
        "{%0,%1,%2,%3}, {%4,%5,%6,%7}, {%8,%9}, {%0,%1,%2,%3};"
        : "+f"(d[0]), "+f"(d[1]), "+f"(d[2]), "+f"(d[3])
        : "r"(a[0]), "r"(a[1]), "r"(a[2]), "r"(a[3]), "r"(b[0]), "r"(b[1]));
}
__device__ __forceinline__ void sig_add(unsigned int* p, unsigned int v) {
    asm volatile("red.release.gpu.global.add.u32 [%0], %1;" :: "l"(p), "r"(v) : "memory");
}
__device__ __forceinline__ unsigned int ld_acq(const unsigned int* p) {
    unsigned int v;
    asm volatile("ld.acquire.gpu.global.u32 %0, [%1];" : "=r"(v) : "l"(p) : "memory");
    return v;
}
__device__ __forceinline__ void poll_ge(const unsigned int* p, unsigned int tgt) {
    while (ld_acq(p) < tgt) { __nanosleep(32); }
}
__device__ __forceinline__ void cp16(uint32_t dst, const void* src) {
    asm volatile("cp.async.cg.shared.global [%0], [%1], 16;" :: "r"(dst), "l"(src) : "memory");
}
__device__ __forceinline__ void cp_commit() {
    asm volatile("cp.async.commit_group;" ::: "memory");
}
__device__ __forceinline__ void cp_waitg0() {
    asm volatile("cp.async.wait_group 0;" ::: "memory");
}
__device__ __forceinline__ void cp_waitg1() {
    asm volatile("cp.async.wait_group 1;" ::: "memory");
}
__device__ __forceinline__ void named_bar(int id) {
    asm volatile("bar.sync %0, 128;" :: "r"(id) : "memory");
}

// ---------------- templated main loop (KS_T: ksteps per wk half, constexpr) ----
template <int KS_T>
__device__ __forceinline__ void run_loop(
    char* sm, uint32_t smb, float (*sm_out)[25],
    int tid, int lane, int wg_tid, int wk, int wm,
    int ks, int n0, bool inp,
    const float* __restrict__ tonic, float* __restrict__ out,
    int Rrows, int nbase, unsigned int bar)
{
    constexpr int KH_T = KS_T / 2;
    const int kkbase = wk * KS_T;
    const float AC = 0.1f, OMA = 0.9f;
    float* ex = (float*)(sm + B_OFF);

    // ---- preload A fragments into registers (persist all 512 steps) ----
    const uint32_t aBase = smb + A_OFF
        + (uint32_t)(wm * 32 + (lane & 15)) * A_STRIDE + (uint32_t)(lane >> 4) * 16;
    uint32_t af[KS_T][2][4];
#pragma unroll
    for (int j = 0; j < KS_T; ++j) {
        const uint32_t aA = aBase + (uint32_t)(kkbase + j) * 32;
        ldsm4(af[j][0], aA);
        ldsm4(af[j][1], aA + 16 * A_STRIDE);
    }

    const uint32_t bBase = smb + B_OFF
        + (uint32_t)((lane & 7) + ((lane >> 3) & 1) * 8) * B_STRIDE
        + (uint32_t)(lane >> 4) * 16;

    for (int t = 0; t < TT; ++t) {
        const float* __restrict__ cur = g_h[t & 1];
        float* __restrict__ nxt = g_h[(t + 1) & 1];

        // ---- phase 1: B-copy (single fp16 plane) in 2 committed chunks ----
        const char* src = inp ? (const char*)&g_x16[(size_t)t * II * BB]
                              : (const char*)&g_r16[(size_t)(ks * KSLICE) * BB];
        constexpr int half_rows = KS_T * 16;
        constexpr int crows = half_rows / 2;
        const int row0 = wk * half_rows;
#pragma unroll
        for (int ch = 0; ch < 2; ++ch) {
            const int r0c = row0 + ch * crows;
#pragma unroll
            for (int s = 0; s < crows * 8; s += 128) {
                int seg = s + wg_tid;
                int r = r0c + (seg >> 3), c16 = (seg & 7) * 16;
                cp16(smb + B_OFF + r * B_STRIDE + c16, src + r * 128 + c16);
            }
            cp_commit();
        }

        // ---- phase 2: 1-term fp16 MMA (A in regs, B from smem) ----
        float acc[2][8][4];
#pragma unroll
        for (int a = 0; a < 2; ++a)
#pragma unroll
            for (int b = 0; b < 8; ++b)
#pragma unroll
                for (int q = 0; q < 4; ++q) acc[a][b][q] = 0.0f;

        cp_waitg1();
        named_bar(1 + wk);

#pragma unroll
        for (int half = 0; half < 2; ++half) {
#pragma unroll
            for (int j = 0; j < KH_T; ++j) {
                const int js = half * KH_T + j;          // constexpr-foldable
                const int kk = kkbase + js;
                uint32_t bf[8][2];
                const uint32_t bA = bBase + (uint32_t)kk * 16 * B_STRIDE;
                ldsm4t(&bf[0][0], bA);
                ldsm4t(&bf[2][0], bA + 32);
                ldsm4t(&bf[4][0], bA + 64);
                ldsm4t(&bf[6][0], bA + 96);
#pragma unroll
                for (int mt = 0; mt < 2; ++mt)
#pragma unroll
                    for (int nb = 0; nb < 8; ++nb)
                        mma16816(acc[mt][nb], af[js][mt], bf[nb]);
            }
            if (half == 0) {
                cp_waitg0();
                named_bar(1 + wk);
            }
        }

        // ---- phase 3: wk-pair combine in smem, then store slice ks ----
        __syncthreads();                   // all B-frag reads complete
        if (wk == 1) {
#pragma unroll
            for (int mt = 0; mt < 2; ++mt)
#pragma unroll
                for (int nb = 0; nb < 8; ++nb)
                    *(float4*)&ex[wg_tid * 68 + (mt * 8 + nb) * 4] =
                        make_float4(acc[mt][nb][0], acc[mt][nb][1],
                                    acc[mt][nb][2], acc[mt][nb][3]);
        }
        __syncthreads();
        if (wk == 0) {
            float* dst = &g_partial[ks][0];
            const int gi = lane >> 2;
            const int ti = lane & 3;
#pragma unroll
            for (int mt = 0; mt < 2; ++mt) {
                int r0 = n0 + wm * 32 + mt * 16 + gi;
#pragma unroll
                for (int nb = 0; nb < 8; ++nb) {
                    float4 o = *(float4*)&ex[wg_tid * 68 + (mt * 8 + nb) * 4];
                    int cb = nb * 8 + 2 * ti;
                    __stcg((float2*)&dst[(size_t)r0 * BB + cb],
                           make_float2(acc[mt][nb][0] + o.x, acc[mt][nb][1] + o.y));
                    __stcg((float2*)&dst[(size_t)(r0 + 8) * BB + cb],
                           make_float2(acc[mt][nb][2] + o.z, acc[mt][nb][3] + o.w));
                }
            }
        }

        // ---- barrier 1: partials visible ----
        bar += GRID;
        __syncthreads();
        if (tid == 0) { sig_add(&g_arrive, 1u); poll_ge(&g_arrive, bar); }
        __syncthreads();

        // ---- phase 4: distributed reduce + update + relu + publish r ----
        for (int u = tid; u < Rrows * 16; u += NTHREADS) {
            int row = u >> 4;
            int b0 = (u & 15) * 4;
            int n = nbase + row;
            size_t off = (size_t)n * BB + b0;

            float4 s = make_float4(0.f, 0.f, 0.f, 0.f);
#pragma unroll
            for (int p = 0; p < NSL; ++p) {
                float4 q = __ldcg((const float4*)&g_partial[p][off]);
                s.x += q.x; s.y += q.y; s.z += q.z; s.w += q.w;
            }
            float tn = __ldg(&tonic[n]);
            float4 hv = __ldcg((const float4*)&cur[off]);
            float4 r4;
            r4.x = OMA * hv.x + AC * (s.x + tn);
            r4.y = OMA * hv.y + AC * (s.y + tn);
            r4.z = OMA * hv.z + AC * (s.z + tn);
            r4.w = OMA * hv.w + AC * (s.w + tn);
            __stcg((float4*)&nxt[off], r4);

            float rr[4] = {fmaxf(r4.x, 0.f), fmaxf(r4.y, 0.f),
                           fmaxf(r4.z, 0.f), fmaxf(r4.w, 0.f)};
            sm_out[b0 + 0][row] = rr[0];
            sm_out[b0 + 1][row] = rr[1];
            sm_out[b0 + 2][row] = rr[2];
            sm_out[b0 + 3][row] = rr[3];

            __half2 r01 = __floats2half2_rn(rr[0], rr[1]);
            __half2 r23 = __floats2half2_rn(rr[2], rr[3]);
            uint2 pk;
            pk.x = *(uint32_t*)&r01;
            pk.y = *(uint32_t*)&r23;
            *(uint2*)&g_r16[off] = pk;
        }

        // ---- barrier 2 with out-writes overlapped into the wait ----
        bar += GRID;
        __syncthreads();
        if (tid == 0) sig_add(&g_arrive, 1u);
        for (int idx = tid; idx < Rrows * 64; idx += NTHREADS) {
            int b = idx / Rrows;
            int rr2 = idx - b * Rrows;
            out[((size_t)b * TT + t) * NN + nbase + rr2] = sm_out[b][rr2];
        }
        if (tid == 0) poll_ge(&g_arrive, bar);
        __syncthreads();
    }
}

// ---------------- persistent RNN kernel ----------------
__global__ void __launch_bounds__(NTHREADS, 1) rnn_persistent(
    const float* __restrict__ x,      // [B,T,I]
    const float* __restrict__ h0,     // [B,N]
    const float* __restrict__ Wrec,   // [N,N]
    const float* __restrict__ Winp,   // [N,I]
    const float* __restrict__ tonic,  // [N]
    const int*   __restrict__ mask,   // [N,N]
    const int*   __restrict__ sgn,    // [N,N]
    float* __restrict__ out)          // [B,T,N]
{
    extern __shared__ __align__(16) char sm[];
    const uint32_t smb = smem_u32(sm);
    __shared__ float sm_out[64][25];   // out staging [b][row], rows<=24

    const int cta = blockIdx.x;
    const int nt  = cta % NTILES;
    const int ks  = cta / NTILES;
    const int n0  = nt * 128;
    const int k0  = ks * KSLICE;
    const int tid = threadIdx.x;
    const int wid = tid >> 5;
    const int lane = tid & 31;
    const int wg_tid = tid & 127;
    const bool inp = (ks == KSP - 1);

    // warp grid: wm = wid&3 (32-row slabs), wk = wid>>2 (k halves)
    const int wm = wid & 3;
    const int wk = wid >> 2;

    // ======== prologue (once per launch) ========
    // A (W slice) -> smem, single fp16 plane
    for (int idx = tid; idx < 128 * 256; idx += NTHREADS) {
        int m = idx >> 8, c = idx & 255;
        int n = n0 + m;
        float v = 0.0f;
        if (!inp) {
            int k = k0 + c;
            float w = Wrec[(size_t)n * NN + k];
            int ms = mask[(size_t)n * NN + k] * sgn[(size_t)n * NN + k];
            v = fmaxf(w, 0.0f) * (float)ms;
        } else if (c < II) {
            v = Winp[(size_t)n * II + c];
        }
        *(__half*)(sm + A_OFF + m * A_STRIDE + c * 2) = __float2half(v);
    }
    // h0 -> g_h[0] and g_r16 ([n][b] layout)
    {
        int gid = cta * NTHREADS + tid;
        if (gid < (NN * BB) / 4) {
            int base = gid * 4;
            int n = base >> 6, b0 = base & 63;
            float hv[4];
#pragma unroll
            for (int u = 0; u < 4; ++u) hv[u] = h0[(size_t)(b0 + u) * NN + n];
            *(float4*)&g_h[0][base] = make_float4(hv[0], hv[1], hv[2], hv[3]);
            __half2 r01 = __floats2half2_rn(fmaxf(hv[0], 0.f), fmaxf(hv[1], 0.f));
            __half2 r23 = __floats2half2_rn(fmaxf(hv[2], 0.f), fmaxf(hv[3], 0.f));
            uint2 pk;
            pk.x = *(uint32_t*)&r01;
            pk.y = *(uint32_t*)&r23;
            *(uint2*)&g_r16[base] = pk;
        }
    }
    // x -> g_x16 ([t][i][b] layout)
    for (int gid = cta * NTHREADS + tid; gid < (TT * II * BB) / 4; gid += GRID * NTHREADS) {
        int base = gid * 4;
        int b0 = base & 63;
        int i  = (base >> 6) & (II - 1);
        int t  = base >> 13;
        float v0 = __ldg(&x[((size_t)(b0 + 0) * TT + t) * II + i]);
        float v1 = __ldg(&x[((size_t)(b0 + 1) * TT + t) * II + i]);
        float v2 = __ldg(&x[((size_t)(b0 + 2) * TT + t) * II + i]);
        float v3 = __ldg(&x[((size_t)(b0 + 3) * TT + t) * II + i]);
        __half2 x01 = __floats2half2_rn(v0, v1);
        __half2 x23 = __floats2half2_rn(v2, v3);
        uint2 pk;
        pk.x = *(uint32_t*)&x01;
        pk.y = *(uint32_t*)&x23;
        *(uint2*)&g_x16[base] = pk;
    }

    // prologue barrier
    unsigned int bar = GRID;
    __threadfence();
    __syncthreads();
    if (tid == 0) { sig_add(&g_arrive, 1u); poll_ge(&g_arrive, bar); }
    __syncthreads();

    // reduce ownership (input CTAs take more rows)
    const int Rrows = inp ? 24 : 13;
    const int nbase = inp ? (1664 + nt * 24) : (cta * 13);

    if (inp) {
        run_loop<4>(sm, smb, sm_out, tid, lane, wg_tid, wk, wm,
                    ks, n0, true, tonic, out, Rrows, nbase, bar);
    } else {
        run_loop<8>(sm, smb, sm_out, tid, lane, wg_tid, wk, wm,
                    ks, n0, false, tonic, out, Rrows, nbase, bar);
    }
}

// ---------------- launch ----------------
extern "C" void kernel_launch(void* const* d_in, const int* in_sizes, int n_in,
                              void* d_out, int out_size) {
    const float* x     = (const float*)d_in[0];
    const float* h0    = (const float*)d_in[1];
    const float* Wrec  = (const float*)d_in[2];
    const float* Winp  = (const float*)d_in[3];
    const float* tonic = (const float*)d_in[4];
    const int*   mask  = (const int*)d_in[5];
    const int*   sgn   = (const int*)d_in[6];
    float* out = (float*)d_out;

    cudaFuncSetAttribute(rnn_persistent,
                         cudaFuncAttributeMaxDynamicSharedMemorySize, SMEM_DYN);

    void* pa = nullptr;
    cudaGetSymbolAddress(&pa, g_arrive);
    cudaMemsetAsync(pa, 0, sizeof(unsigned int));

    rnn_persistent<<<GRID, NTHREADS, SMEM_DYN>>>(x, h0, Wrec, Winp, tonic,
                                                 mask, sgn, out);
}

// round 15
// speedup vs baseline: 1.3835x; 1.1667x over previous
#include <cuda_runtime.h>
#include <cuda_fp16.h>
#include <cstdint>

// ---------------- problem dims ----------------
#define BB 64
#define TT 512
#define II 128
#define NN 2048
#define NTILES 16
#define KSP 9                 // 8 recurrent k-slices of 256 + 1 input slice
#define KSLICE 256
#define NSL 9                 // partial slices (wk pair pre-combined in CTA)
#define GRID (NTILES * KSP)   // 144 CTAs, co-resident (1 per SM)
#define NTHREADS 256

// ---------------- smem layout (bytes) ----------------
#define A_STRIDE 528                       // 256 fp16 + 16B pad
#define B_STRIDE 144                       // 64 fp16 + 16B pad
#define A_OFF 0
#define B_OFF (128 * A_STRIDE)             // 67584
#define EX_OFF (B_OFF + 256 * B_STRIDE)    // 104448 (dedicated exchange)
#define SMEM_DYN (EX_OFF + 128 * 68 * 4)   // 139264

// ---------------- device globals ----------------
__device__ float g_partial[2][NSL][NN * BB];     // split-K partials, ping-pong
__device__ __half g_r16[2][NN * BB];             // relu(h) fp16 ping-pong, [n][b]
__device__ __half g_x16[TT * II * BB];           // x fp16, [t][i][b]
__device__ unsigned int g_sync[1024];            // P[nt]@nt*32, RDY[s]@512+s*32, ARRIVE@768

#define P_CTR(nt)  (&g_sync[(nt) * 32])
#define RDY_CTR(s) (&g_sync[512 + (s) * 32])
#define ARRIVE     (&g_sync[768])

// ---------------- helpers ----------------
__device__ __forceinline__ uint32_t smem_u32(const void* p) {
    uint32_t a;
    asm("{ .reg .u64 t; cvta.to.shared.u64 t, %1; cvt.u32.u64 %0, t; }" : "=r"(a) : "l"(p));
    return a;
}
__device__ __forceinline__ void ldsm4(uint32_t* r, uint32_t addr) {
    asm volatile("ldmatrix.sync.aligned.m8n8.x4.shared.b16 {%0,%1,%2,%3}, [%4];"
                 : "=r"(r[0]), "=r"(r[1]), "=r"(r[2]), "=r"(r[3]) : "r"(addr));
}
__device__ __forceinline__ void ldsm4t(uint32_t* r, uint32_t addr) {
    asm volatile("ldmatrix.sync.aligned.m8n8.x4.trans.shared.b16 {%0,%1,%2,%3}, [%4];"
                 : "=r"(r[0]), "=r"(r[1]), "=r"(r[2]), "=r"(r[3]) : "r"(addr));
}
__device__ __forceinline__ void mma16816(float* d, const uint32_t* a, const uint32_t* b) {
    asm volatile(
        "mma.sync.aligned.m16n8k16.row.col.f32.f16.f16.f32 "
        "{%0,%1,%2,%3}, {%4,%5,%6,%7}, {%8,%9}, {%0,%1,%2,%3};"
        : "+f"(d[0]), "+f"(d[1]), "+f"(d[2]), "+f"(d[3])
        : "r"(a[0]), "r"(a[1]), "r"(a[2]), "r"(a[3]), "r"(b[0]), "r"(b[1]));
}
__device__ __forceinline__ void sig_add(unsigned int* p, unsigned int v) {
    asm volatile("red.release.gpu.global.add.u32 [%0], %1;" :: "l"(p), "r"(v) : "memory");
}
__device__ __forceinline__ unsigned int ld_acq(const unsigned int* p) {
    unsigned int v;
    asm volatile("ld.acquire.gpu.global.u32 %0, [%1];" : "=r"(v) : "l"(p) : "memory");
    return v;
}
__device__ __forceinline__ void poll_ge(const unsigned int* p, unsigned int tgt) {
    while (ld_acq(p) < tgt) { __nanosleep(32); }
}
__device__ __forceinline__ void cp16(uint32_t dst, const void* src) {
    asm volatile("cp.async.cg.shared.global [%0], [%1], 16;" :: "r"(dst), "l"(src) : "memory");
}
__device__ __forceinline__ void cp_commit() {
    asm volatile("cp.async.commit_group;" ::: "memory");
}
__device__ __forceinline__ void cp_waitg0() {
    asm volatile("cp.async.wait_group 0;" ::: "memory");
}
__device__ __forceinline__ void cp_waitg1() {
    asm volatile("cp.async.wait_group 1;" ::: "memory");
}
__device__ __forceinline__ void named_bar(int id) {
    asm volatile("bar.sync %0, 128;" :: "r"(id) : "memory");
}

// ---------------- templated main loop ----------------
// KS_T: ksteps per wk half (constexpr); RED: this CTA is a reducer (ks<8)
template <int KS_T, bool RED>
__device__ __forceinline__ void run_loop(
    char* sm, uint32_t smb, float (*sm_out)[17],
    int tid, int lane, int wg_tid, int wk, int wm,
    int ks, int nt, int n0,
    float4 h4, float tn,
    float* __restrict__ out)
{
    constexpr int KH_T = KS_T / 2;
    const int kkbase = wk * KS_T;
    const float AC = 0.1f, OMA = 0.9f;
    float* ex = (float*)(sm + EX_OFF);

    // reducer identity: rows [redN, redN+16)
    const int redN = RED ? (256 * ks + 16 * nt) : 0;
    const int tileT = RED ? (redN >> 7) : 0;
    const int myrow = tid >> 4;               // 0..15
    const int myb0 = (tid & 15) * 4;
    const size_t myoff = (size_t)(redN + myrow) * BB + myb0;

    // ---- preload A fragments into registers (persist all 512 steps) ----
    const uint32_t aBase = smb + A_OFF
        + (uint32_t)(wm * 32 + (lane & 15)) * A_STRIDE + (uint32_t)(lane >> 4) * 16;
    uint32_t af[KS_T][2][4];
#pragma unroll
    for (int j = 0; j < KS_T; ++j) {
        const uint32_t aA = aBase + (uint32_t)(kkbase + j) * 32;
        ldsm4(af[j][0], aA);
        ldsm4(af[j][1], aA + 16 * A_STRIDE);
    }

    const uint32_t bBase = smb + B_OFF
        + (uint32_t)((lane & 7) + ((lane >> 3) & 1) * 8) * B_STRIDE
        + (uint32_t)(lane >> 4) * 16;

    for (int t = 0; t < TT; ++t) {
        const int par = t & 1;

        // ---- gate B-copy: my r slice ready (recurrent only) ----
        if (RED && t > 0) {
            if (tid == 0) poll_ge(RDY_CTR(ks), 16u * (unsigned)t);
            __syncthreads();
        }

        // ---- phase 1: B-copy in 2 committed chunks ----
        const char* src = RED ? (const char*)&g_r16[par][(size_t)(ks * KSLICE) * BB]
                              : (const char*)&g_x16[(size_t)t * II * BB];
        constexpr int half_rows = KS_T * 16;
        constexpr int crows = half_rows / 2;
        const int row0 = wk * half_rows;
#pragma unroll
        for (int ch = 0; ch < 2; ++ch) {
            const int r0c = row0 + ch * crows;
#pragma unroll
            for (int s = 0; s < crows * 8; s += 128) {
                int seg = s + wg_tid;
                int r = r0c + (seg >> 3), c16 = (seg & 7) * 16;
                cp16(smb + B_OFF + r * B_STRIDE + c16, src + r * 128 + c16);
            }
            cp_commit();
        }

        // ---- phase 2: 1-term fp16 MMA (A in regs, B from smem) ----
        float acc[2][8][4];
#pragma unroll
        for (int a = 0; a < 2; ++a)
#pragma unroll
            for (int b = 0; b < 8; ++b)
#pragma unroll
                for (int q = 0; q < 4; ++q) acc[a][b][q] = 0.0f;

        cp_waitg1();
        named_bar(1 + wk);

#pragma unroll
        for (int half = 0; half < 2; ++half) {
#pragma unroll
            for (int j = 0; j < KH_T; ++j) {
                const int js = half * KH_T + j;
                const int kk = kkbase + js;
                uint32_t bf[8][2];
                const uint32_t bA = bBase + (uint32_t)kk * 16 * B_STRIDE;
                ldsm4t(&bf[0][0], bA);
                ldsm4t(&bf[2][0], bA + 32);
                ldsm4t(&bf[4][0], bA + 64);
                ldsm4t(&bf[6][0], bA + 96);
#pragma unroll
                for (int mt = 0; mt < 2; ++mt)
#pragma unroll
                    for (int nb = 0; nb < 8; ++nb)
                        mma16816(acc[mt][nb], af[js][mt], bf[nb]);
            }
            if (half == 0) {
                cp_waitg0();
                named_bar(1 + wk);
            }
        }

        // ---- phase 3: wk-pair combine (dedicated ex smem), store slice ks ----
        if (wk == 1) {
#pragma unroll
            for (int mt = 0; mt < 2; ++mt)
#pragma unroll
                for (int nb = 0; nb < 8; ++nb)
                    *(float4*)&ex[wg_tid * 68 + (mt * 8 + nb) * 4] =
                        make_float4(acc[mt][nb][0], acc[mt][nb][1],
                                    acc[mt][nb][2], acc[mt][nb][3]);
        }
        // input CTAs: gate partial overwrite on their rows' readers (t-1 reducers)
        if (!RED && t > 0 && tid == 0)
            poll_ge(RDY_CTR(nt >> 1), 16u * (unsigned)t);
        __syncthreads();
        if (wk == 0) {
            float* dst = &g_partial[par][ks][0];
            const int gi = lane >> 2;
            const int ti = lane & 3;
#pragma unroll
            for (int mt = 0; mt < 2; ++mt) {
                int r0 = n0 + wm * 32 + mt * 16 + gi;
#pragma unroll
                for (int nb = 0; nb < 8; ++nb) {
                    float4 o = *(float4*)&ex[wg_tid * 68 + (mt * 8 + nb) * 4];
                    int cb = nb * 8 + 2 * ti;
                    __stcg((float2*)&dst[(size_t)r0 * BB + cb],
                           make_float2(acc[mt][nb][0] + o.x, acc[mt][nb][1] + o.y));
                    __stcg((float2*)&dst[(size_t)(r0 + 8) * BB + cb],
                           make_float2(acc[mt][nb][2] + o.z, acc[mt][nb][3] + o.w));
                }
            }
        }
        __syncthreads();
        if (tid == 0) sig_add(P_CTR(nt), 1u);

        // ---- phase 4 (reducers only): reduce 16 rows, update h, publish r ----
        if (RED) {
            if (tid == 0) poll_ge(P_CTR(tileT), 9u * (unsigned)(t + 1));
            __syncthreads();

            float4 s = make_float4(0.f, 0.f, 0.f, 0.f);
#pragma unroll
            for (int p = 0; p < NSL; ++p) {
                float4 q = __ldcg((const float4*)&g_partial[par][p][myoff]);
                s.x += q.x; s.y += q.y; s.z += q.z; s.w += q.w;
            }
            h4.x = OMA * h4.x + AC * (s.x + tn);
            h4.y = OMA * h4.y + AC * (s.y + tn);
            h4.z = OMA * h4.z + AC * (s.z + tn);
            h4.w = OMA * h4.w + AC * (s.w + tn);

            float rr[4] = {fmaxf(h4.x, 0.f), fmaxf(h4.y, 0.f),
                           fmaxf(h4.z, 0.f), fmaxf(h4.w, 0.f)};
            __half2 r01 = __floats2half2_rn(rr[0], rr[1]);
            __half2 r23 = __floats2half2_rn(rr[2], rr[3]);
            uint2 pk;
            pk.x = *(uint32_t*)&r01;
            pk.y = *(uint32_t*)&r23;
            *(uint2*)&g_r16[par ^ 1][myoff] = pk;

            sm_out[myb0 + 0][myrow] = rr[0];
            sm_out[myb0 + 1][myrow] = rr[1];
            sm_out[myb0 + 2][myrow] = rr[2];
            sm_out[myb0 + 3][myrow] = rr[3];

            __syncthreads();
            if (tid == 0) sig_add(RDY_CTR(ks), 1u);

            // out writes (off critical path)
            for (int idx = tid; idx < 16 * 64; idx += NTHREADS) {
                int b = idx >> 4;
                int r2 = idx & 15;
                out[((size_t)b * TT + t) * NN + redN + r2] = sm_out[b][r2];
            }
        }
    }
}

// ---------------- persistent RNN kernel ----------------
__global__ void __launch_bounds__(NTHREADS, 1) rnn_persistent(
    const float* __restrict__ x,      // [B,T,I]
    const float* __restrict__ h0,     // [B,N]
    const float* __restrict__ Wrec,   // [N,N]
    const float* __restrict__ Winp,   // [N,I]
    const float* __restrict__ tonic,  // [N]
    const int*   __restrict__ mask,   // [N,N]
    const int*   __restrict__ sgn,    // [N,N]
    float* __restrict__ out)          // [B,T,N]
{
    extern __shared__ __align__(16) char sm[];
    const uint32_t smb = smem_u32(sm);
    __shared__ float sm_out[64][17];

    const int cta = blockIdx.x;
    const int nt  = cta % NTILES;
    const int ks  = cta / NTILES;
    const int n0  = nt * 128;
    const int k0  = ks * KSLICE;
    const int tid = threadIdx.x;
    const int wid = tid >> 5;
    const int lane = tid & 31;
    const int wg_tid = tid & 127;
    const bool inp = (ks == KSP - 1);

    const int wm = wid & 3;
    const int wk = wid >> 2;

    // ======== prologue (once per launch) ========
    // A (W slice) -> smem, single fp16 plane
    for (int idx = tid; idx < 128 * 256; idx += NTHREADS) {
        int m = idx >> 8, c = idx & 255;
        int n = n0 + m;
        float v = 0.0f;
        if (!inp) {
            int k = k0 + c;
            float w = Wrec[(size_t)n * NN + k];
            int ms = mask[(size_t)n * NN + k] * sgn[(size_t)n * NN + k];
            v = fmaxf(w, 0.0f) * (float)ms;
        } else if (c < II) {
            v = Winp[(size_t)n * II + c];
        }
        *(__half*)(sm + A_OFF + m * A_STRIDE + c * 2) = __float2half(v);
    }
    // r16[0] init from h0 ([n][b] layout)
    {
        int gid = cta * NTHREADS + tid;
        if (gid < (NN * BB) / 4) {
            int base = gid * 4;
            int n = base >> 6, b0 = base & 63;
            float hv[4];
#pragma unroll
            for (int u = 0; u < 4; ++u) hv[u] = h0[(size_t)(b0 + u) * NN + n];
            __half2 r01 = __floats2half2_rn(fmaxf(hv[0], 0.f), fmaxf(hv[1], 0.f));
            __half2 r23 = __floats2half2_rn(fmaxf(hv[2], 0.f), fmaxf(hv[3], 0.f));
            uint2 pk;
            pk.x = *(uint32_t*)&r01;
            pk.y = *(uint32_t*)&r23;
            *(uint2*)&g_r16[0][base] = pk;
        }
    }
    // x -> g_x16 ([t][i][b] layout)
    for (int gid = cta * NTHREADS + tid; gid < (TT * II * BB) / 4; gid += GRID * NTHREADS) {
        int base = gid * 4;
        int b0 = base & 63;
        int i  = (base >> 6) & (II - 1);
        int t  = base >> 13;
        float v0 = __ldg(&x[((size_t)(b0 + 0) * TT + t) * II + i]);
        float v1 = __ldg(&x[((size_t)(b0 + 1) * TT + t) * II + i]);
        float v2 = __ldg(&x[((size_t)(b0 + 2) * TT + t) * II + i]);
        float v3 = __ldg(&x[((size_t)(b0 + 3) * TT + t) * II + i]);
        __half2 x01 = __floats2half2_rn(v0, v1);
        __half2 x23 = __floats2half2_rn(v2, v3);
        uint2 pk;
        pk.x = *(uint32_t*)&x01;
        pk.y = *(uint32_t*)&x23;
        *(uint2*)&g_x16[base] = pk;
    }

    // reducer h/tonic registers (rows [256ks+16nt, +16), one (row,b4) per thread)
    float4 h4 = make_float4(0.f, 0.f, 0.f, 0.f);
    float tn = 0.0f;
    if (!inp) {
        int n = 256 * ks + 16 * nt + (tid >> 4);
        int b0 = (tid & 15) * 4;
        h4.x = h0[(size_t)(b0 + 0) * NN + n];
        h4.y = h0[(size_t)(b0 + 1) * NN + n];
        h4.z = h0[(size_t)(b0 + 2) * NN + n];
        h4.w = h0[(size_t)(b0 + 3) * NN + n];
        tn = tonic[n];
    }

    // one-time global barrier after prologue
    __threadfence();
    __syncthreads();
    if (tid == 0) { sig_add(ARRIVE, 1u); poll_ge(ARRIVE, GRID); }
    __syncthreads();

    if (inp) {
        run_loop<4, false>(sm, smb, sm_out, tid, lane, wg_tid, wk, wm,
                           ks, nt, n0, h4, tn, out);
    } else {
        run_loop<8, true>(sm, smb, sm_out, tid, lane, wg_tid, wk, wm,
                          ks, nt, n0, h4, tn, out);
    }
}

// ---------------- launch ----------------
extern "C" void kernel_launch(void* const* d_in, const int* in_sizes, int n_in,
                              void* d_out, int out_size) {
    const float* x     = (const float*)d_in[0];
    const float* h0    = (const float*)d_in[1];
    const float* Wrec  = (const float*)d_in[2];
    const float* Winp  = (const float*)d_in[3];
    const float* tonic = (const float*)d_in[4];
    const int*   mask  = (const int*)d_in[5];
    const int*   sgn   = (const int*)d_in[6];
    float* out = (float*)d_out;

    cudaFuncSetAttribute(rnn_persistent,
                         cudaFuncAttributeMaxDynamicSharedMemorySize, SMEM_DYN);

    void* pa = nullptr;
    cudaGetSymbolAddress(&pa, g_sync);
    cudaMemsetAsync(pa, 0, sizeof(unsigned int) * 1024);

    rnn_persistent<<<GRID, NTHREADS, SMEM_DYN>>>(x, h0, Wrec, Winp, tonic,
                                                 mask, sgn, out);
}

// round 17
// speedup vs baseline: 1.3949x; 1.0082x over previous
#include <cuda_runtime.h>
#include <cuda_fp16.h>
#include <cstdint>

// ---------------- problem dims ----------------
#define BB 64
#define TT 512
#define II 128
#define NN 2048
#define NTILES 16
#define KSP 9                 // 8 recurrent k-slices of 256 + 1 input slice
#define KSLICE 256
#define NSL 9                 // partial slices (wk pair pre-combined in CTA)
#define GRID (NTILES * KSP)   // 144 CTAs, co-resident (1 per SM)
#define NTHREADS 256

// ---------------- smem layout (bytes) ----------------
#define A_STRIDE 528                       // 256 fp16 + 16B pad
#define B_STRIDE 144                       // 64 fp16 + 16B pad
#define A_OFF 0
#define B_OFF (128 * A_STRIDE)             // 67584
#define EX_OFF (B_OFF + 256 * B_STRIDE)    // 104448 (dedicated exchange)
#define SMEM_DYN (EX_OFF + 128 * 68 * 4)   // 139264

// ---------------- device globals ----------------
__device__ float g_partial[2][NSL][NN * BB];     // split-K partials, ping-pong
__device__ __half g_r16[2][NN * BB];             // relu(h) fp16 ping-pong, [n][b]
__device__ __half g_x16[TT * II * BB];           // x fp16, [t][i][b]
// P[nt] @ nt*32 (words 0..480), RDY2[s][h] @ 512+(s*2+h)*32 (words 512..992),
// ARRIVE @ 1024 (collision-free; R16 had it at 960 == RDY2(7,0) -> 12% error)
__device__ unsigned int g_sync[1088];

#define P_CTR(nt)       (&g_sync[(nt) * 32])
#define RDY2_CTR(s, h)  (&g_sync[512 + ((s) * 2 + (h)) * 32])
#define ARRIVE          (&g_sync[1024])

// ---------------- helpers ----------------
__device__ __forceinline__ uint32_t smem_u32(const void* p) {
    uint32_t a;
    asm("{ .reg .u64 t; cvta.to.shared.u64 t, %1; cvt.u32.u64 %0, t; }" : "=r"(a) : "l"(p));
    return a;
}
__device__ __forceinline__ void ldsm4(uint32_t* r, uint32_t addr) {
    asm volatile("ldmatrix.sync.aligned.m8n8.x4.shared.b16 {%0,%1,%2,%3}, [%4];"
                 : "=r"(r[0]), "=r"(r[1]), "=r"(r[2]), "=r"(r[3]) : "r"(addr));
}
__device__ __forceinline__ void ldsm4t(uint32_t* r, uint32_t addr) {
    asm volatile("ldmatrix.sync.aligned.m8n8.x4.trans.shared.b16 {%0,%1,%2,%3}, [%4];"
                 : "=r"(r[0]), "=r"(r[1]), "=r"(r[2]), "=r"(r[3]) : "r"(addr));
}
__device__ __forceinline__ void mma16816(float* d, const uint32_t* a, const uint32_t* b) {
    asm volatile(
        "mma.sync.aligned.m16n8k16.row.col.f32.f16.f16.f32 "
        "{%0,%1,%2,%3}, {%4,%5,%6,%7}, {%8,%9}, {%0,%1,%2,%3};"
        : "+f"(d[0]), "+f"(d[1]), "+f"(d[2]), "+f"(d[3])
        : "r"(a[0]), "r"(a[1]), "r"(a[2]), "r"(a[3]), "r"(b[0]), "r"(b[1]));
}
__device__ __forceinline__ void sig_add(unsigned int* p, unsigned int v) {
    asm volatile("red.release.gpu.global.add.u32 [%0], %1;" :: "l"(p), "r"(v) : "memory");
}
__device__ __forceinline__ unsigned int ld_acq(const unsigned int* p) {
    unsigned int v;
    asm volatile("ld.acquire.gpu.global.u32 %0, [%1];" : "=r"(v) : "l"(p) : "memory");
    return v;
}
__device__ __forceinline__ void poll_ge(const unsigned int* p, unsigned int tgt) {
    while (ld_acq(p) < tgt) { }   // tight spin: ld.acquire round-trip is the backoff
}
__device__ __forceinline__ void cp16(uint32_t dst, const void* src) {
    asm volatile("cp.async.cg.shared.global [%0], [%1], 16;" :: "r"(dst), "l"(src) : "memory");
}
__device__ __forceinline__ void cp_commit() {
    asm volatile("cp.async.commit_group;" ::: "memory");
}
__device__ __forceinline__ void cp_waitg0() {
    asm volatile("cp.async.wait_group 0;" ::: "memory");
}
__device__ __forceinline__ void cp_waitg1() {
    asm volatile("cp.async.wait_group 1;" ::: "memory");
}
__device__ __forceinline__ void named_bar(int id) {
    asm volatile("bar.sync %0, 128;" :: "r"(id) : "memory");
}

// ---------------- templated main loop ----------------
// KS_T: ksteps per wk half (constexpr); RED: this CTA is a reducer (ks<8)
template <int KS_T, bool RED>
__device__ __forceinline__ void run_loop(
    char* sm, uint32_t smb, float (*sm_out)[17],
    int tid, int lane, int wg_tid, int wk, int wm,
    int ks, int nt, int n0,
    float4 h4, float tn,
    float* __restrict__ out)
{
    constexpr int KH_T = KS_T / 2;
    const int kkbase = wk * KS_T;
    const float AC = 0.1f, OMA = 0.9f;
    float* ex = (float*)(sm + EX_OFF);

    // reducer identity: rows [redN, redN+16)
    const int redN = RED ? (256 * ks + 16 * nt) : 0;
    const int tileT = RED ? (redN >> 7) : 0;
    const int myrow = tid >> 4;               // 0..15
    const int myb0 = (tid & 15) * 4;
    const size_t myoff = (size_t)(redN + myrow) * BB + myb0;

    // ---- preload A fragments into registers (persist all 512 steps) ----
    const uint32_t aBase = smb + A_OFF
        + (uint32_t)(wm * 32 + (lane & 15)) * A_STRIDE + (uint32_t)(lane >> 4) * 16;
    uint32_t af[KS_T][2][4];
#pragma unroll
    for (int j = 0; j < KS_T; ++j) {
        const uint32_t aA = aBase + (uint32_t)(kkbase + j) * 32;
        ldsm4(af[j][0], aA);
        ldsm4(af[j][1], aA + 16 * A_STRIDE);
    }

    const uint32_t bBase = smb + B_OFF
        + (uint32_t)((lane & 7) + ((lane >> 3) & 1) * 8) * B_STRIDE
        + (uint32_t)(lane >> 4) * 16;

    for (int t = 0; t < TT; ++t) {
        const int par = t & 1;

        // ---- per-wk-group gate: my half of the r slice ready ----
        if (RED && t > 0) {
            if (wg_tid == 0) poll_ge(RDY2_CTR(ks, wk), 8u * (unsigned)t);
            named_bar(1 + wk);
        }

        // ---- phase 1: B-copy in 2 committed chunks (per wk group) ----
        const char* src = RED ? (const char*)&g_r16[par][(size_t)(ks * KSLICE) * BB]
                              : (const char*)&g_x16[(size_t)t * II * BB];
        constexpr int half_rows = KS_T * 16;
        constexpr int crows = half_rows / 2;
        const int row0 = wk * half_rows;
#pragma unroll
        for (int ch = 0; ch < 2; ++ch) {
            const int r0c = row0 + ch * crows;
#pragma unroll
            for (int s = 0; s < crows * 8; s += 128) {
                int seg = s + wg_tid;
                int r = r0c + (seg >> 3), c16 = (seg & 7) * 16;
                cp16(smb + B_OFF + r * B_STRIDE + c16, src + r * 128 + c16);
            }
            cp_commit();
        }

        // ---- phase 2: 1-term fp16 MMA (A in regs, B from smem) ----
        float acc[2][8][4];
#pragma unroll
        for (int a = 0; a < 2; ++a)
#pragma unroll
            for (int b = 0; b < 8; ++b)
#pragma unroll
                for (int q = 0; q < 4; ++q) acc[a][b][q] = 0.0f;

        cp_waitg1();
        named_bar(1 + wk);

#pragma unroll
        for (int half = 0; half < 2; ++half) {
#pragma unroll
            for (int j = 0; j < KH_T; ++j) {
                const int js = half * KH_T + j;
                const int kk = kkbase + js;
                uint32_t bf[8][2];
                const uint32_t bA = bBase + (uint32_t)kk * 16 * B_STRIDE;
                ldsm4t(&bf[0][0], bA);
                ldsm4t(&bf[2][0], bA + 32);
                ldsm4t(&bf[4][0], bA + 64);
                ldsm4t(&bf[6][0], bA + 96);
#pragma unroll
                for (int mt = 0; mt < 2; ++mt)
#pragma unroll
                    for (int nb = 0; nb < 8; ++nb)
                        mma16816(acc[mt][nb], af[js][mt], bf[nb]);
            }
            if (half == 0) {
                cp_waitg0();
                named_bar(1 + wk);
            }
        }

        // ---- phase 3: wk-pair combine (dedicated ex smem), store slice ks ----
        if (wk == 1) {
#pragma unroll
            for (int mt = 0; mt < 2; ++mt)
#pragma unroll
                for (int nb = 0; nb < 8; ++nb)
                    *(float4*)&ex[wg_tid * 68 + (mt * 8 + nb) * 4] =
                        make_float4(acc[mt][nb][0], acc[mt][nb][1],
                                    acc[mt][nb][2], acc[mt][nb][3]);
        }
        // input CTAs: gate partial overwrite on their rows' exact readers
        if (!RED && t > 0 && tid == 0)
            poll_ge(RDY2_CTR(nt >> 1, nt & 1), 8u * (unsigned)t);
        __syncthreads();
        if (wk == 0) {
            float* dst = &g_partial[par][ks][0];
            const int gi = lane >> 2;
            const int ti = lane & 3;
#pragma unroll
            for (int mt = 0; mt < 2; ++mt) {
                int r0 = n0 + wm * 32 + mt * 16 + gi;
#pragma unroll
                for (int nb = 0; nb < 8; ++nb) {
                    float4 o = *(float4*)&ex[wg_tid * 68 + (mt * 8 + nb) * 4];
                    int cb = nb * 8 + 2 * ti;
                    __stcg((float2*)&dst[(size_t)r0 * BB + cb],
                           make_float2(acc[mt][nb][0] + o.x, acc[mt][nb][1] + o.y));
                    __stcg((float2*)&dst[(size_t)(r0 + 8) * BB + cb],
                           make_float2(acc[mt][nb][2] + o.z, acc[mt][nb][3] + o.w));
                }
            }
        }
        __syncthreads();
        if (tid == 0) sig_add(P_CTR(nt), 1u);

        // ---- phase 4 (reducers only): reduce 16 rows, update h, publish r ----
        if (RED) {
            if (tid == 0) poll_ge(P_CTR(tileT), 9u * (unsigned)(t + 1));
            __syncthreads();

            float4 s = make_float4(0.f, 0.f, 0.f, 0.f);
#pragma unroll
            for (int p = 0; p < NSL; ++p) {
                float4 q = __ldcg((const float4*)&g_partial[par][p][myoff]);
                s.x += q.x; s.y += q.y; s.z += q.z; s.w += q.w;
            }
            h4.x = OMA * h4.x + AC * (s.x + tn);
            h4.y = OMA * h4.y + AC * (s.y + tn);
            h4.z = OMA * h4.z + AC * (s.z + tn);
            h4.w = OMA * h4.w + AC * (s.w + tn);

            float rr[4] = {fmaxf(h4.x, 0.f), fmaxf(h4.y, 0.f),
                           fmaxf(h4.z, 0.f), fmaxf(h4.w, 0.f)};
            __half2 r01 = __floats2half2_rn(rr[0], rr[1]);
            __half2 r23 = __floats2half2_rn(rr[2], rr[3]);
            uint2 pk;
            pk.x = *(uint32_t*)&r01;
            pk.y = *(uint32_t*)&r23;
            *(uint2*)&g_r16[par ^ 1][myoff] = pk;

            sm_out[myb0 + 0][myrow] = rr[0];
            sm_out[myb0 + 1][myrow] = rr[1];
            sm_out[myb0 + 2][myrow] = rr[2];
            sm_out[myb0 + 3][myrow] = rr[3];

            __syncthreads();
            if (tid == 0) sig_add(RDY2_CTR(ks, nt >> 3), 1u);

            // out writes (off critical path)
            for (int idx = tid; idx < 16 * 64; idx += NTHREADS) {
                int b = idx >> 4;
                int r2 = idx & 15;
                out[((size_t)b * TT + t) * NN + redN + r2] = sm_out[b][r2];
            }
        }
    }
}

// ---------------- persistent RNN kernel ----------------
__global__ void __launch_bounds__(NTHREADS, 1) rnn_persistent(
    const float* __restrict__ x,      // [B,T,I]
    const float* __restrict__ h0,     // [B,N]
    const float* __restrict__ Wrec,   // [N,N]
    const float* __restrict__ Winp,   // [N,I]
    const float* __restrict__ tonic,  // [N]
    const int*   __restrict__ mask,   // [N,N]
    const int*   __restrict__ sgn,    // [N,N]
    float* __restrict__ out)          // [B,T,N]
{
    extern __shared__ __align__(16) char sm[];
    const uint32_t smb = smem_u32(sm);
    __shared__ float sm_out[64][17];

    const int cta = blockIdx.x;
    const int nt  = cta % NTILES;
    const int ks  = cta / NTILES;
    const int n0  = nt * 128;
    const int k0  = ks * KSLICE;
    const int tid = threadIdx.x;
    const int wid = tid >> 5;
    const int lane = tid & 31;
    const int wg_tid = tid & 127;
    const bool inp = (ks == KSP - 1);

    const int wm = wid & 3;
    const int wk = wid >> 2;

    // ======== prologue (once per launch) ========
    // A (W slice) -> smem, single fp16 plane
    for (int idx = tid; idx < 128 * 256; idx += NTHREADS) {
        int m = idx >> 8, c = idx & 255;
        int n = n0 + m;
        float v = 0.0f;
        if (!inp) {
            int k = k0 + c;
            float w = Wrec[(size_t)n * NN + k];
            int ms = mask[(size_t)n * NN + k] * sgn[(size_t)n * NN + k];
            v = fmaxf(w, 0.0f) * (float)ms;
        } else if (c < II) {
            v = Winp[(size_t)n * II + c];
        }
        *(__half*)(sm + A_OFF + m * A_STRIDE + c * 2) = __float2half(v);
    }
    // r16[0] init from h0 ([n][b] layout)
    {
        int gid = cta * NTHREADS + tid;
        if (gid < (NN * BB) / 4) {
            int base = gid * 4;
            int n = base >> 6, b0 = base & 63;
            float hv[4];
#pragma unroll
            for (int u = 0; u < 4; ++u) hv[u] = h0[(size_t)(b0 + u) * NN + n];
            __half2 r01 = __floats2half2_rn(fmaxf(hv[0], 0.f), fmaxf(hv[1], 0.f));
            __half2 r23 = __floats2half2_rn(fmaxf(hv[2], 0.f), fmaxf(hv[3], 0.f));
            uint2 pk;
            pk.x = *(uint32_t*)&r01;
            pk.y = *(uint32_t*)&r23;
            *(uint2*)&g_r16[0][base] = pk;
        }
    }
    // x -> g_x16 ([t][i][b] layout)
    for (int gid = cta * NTHREADS + tid; gid < (TT * II * BB) / 4; gid += GRID * NTHREADS) {
        int base = gid * 4;
        int b0 = base & 63;
        int i  = (base >> 6) & (II - 1);
        int t  = base >> 13;
        float v0 = __ldg(&x[((size_t)(b0 + 0) * TT + t) * II + i]);
        float v1 = __ldg(&x[((size_t)(b0 + 1) * TT + t) * II + i]);
        float v2 = __ldg(&x[((size_t)(b0 + 2) * TT + t) * II + i]);
        float v3 = __ldg(&x[((size_t)(b0 + 3) * TT + t) * II + i]);
        __half2 x01 = __floats2half2_rn(v0, v1);
        __half2 x23 = __floats2half2_rn(v2, v3);
        uint2 pk;
        pk.x = *(uint32_t*)&x01;
        pk.y = *(uint32_t*)&x23;
        *(uint2*)&g_x16[base] = pk;
    }

    // reducer h/tonic registers (rows [256ks+16nt, +16), one (row,b4) per thread)
    float4 h4 = make_float4(0.f, 0.f, 0.f, 0.f);
    float tn = 0.0f;
    if (!inp) {
        int n = 256 * ks + 16 * nt + (tid >> 4);
        int b0 = (tid & 15) * 4;
        h4.x = h0[(size_t)(b0 + 0) * NN + n];
        h4.y = h0[(size_t)(b0 + 1) * NN + n];
        h4.z = h0[(size_t)(b0 + 2) * NN + n];
        h4.w = h0[(size_t)(b0 + 3) * NN + n];
        tn = tonic[n];
    }

    // one-time global barrier after prologue
    __threadfence();
    __syncthreads();
    if (tid == 0) { sig_add(ARRIVE, 1u); poll_ge(ARRIVE, GRID); }
    __syncthreads();

    if (inp) {
        run_loop<4, false>(sm, smb, sm_out, tid, lane, wg_tid, wk, wm,
                           ks, nt, n0, h4, tn, out);
    } else {
        run_loop<8, true>(sm, smb, sm_out, tid, lane, wg_tid, wk, wm,
                          ks, nt, n0, h4, tn, out);
    }
}

// ---------------- launch ----------------
extern "C" void kernel_launch(void* const* d_in, const int* in_sizes, int n_in,
                              void* d_out, int out_size) {
    const float* x     = (const float*)d_in[0];
    const float* h0    = (const float*)d_in[1];
    const float* Wrec  = (const float*)d_in[2];
    const float* Winp  = (const float*)d_in[3];
    const float* tonic = (const float*)d_in[4];
    const int*   mask  = (const int*)d_in[5];
    const int*   sgn   = (const int*)d_in[6];
    float* out = (float*)d_out;

    cudaFuncSetAttribute(rnn_persistent,
                         cudaFuncAttributeMaxDynamicSharedMemorySize, SMEM_DYN);

    void* pa = nullptr;
    cudaGetSymbolAddress(&pa, g_sync);
    cudaMemsetAsync(pa, 0, sizeof(unsigned int) * 1088);

    rnn_persistent<<<GRID, NTHREADS, SMEM_DYN>>>(x, h0, Wrec, Winp, tonic,
                                                 mask, sgn, out);
}